// round 5
// baseline (speedup 1.0000x reference)
#include <cuda_runtime.h>
#include <cuda_fp16.h>
#include <math.h>
#include <stdint.h>

#define D_MODEL 1024
#define SEQ     4096
#define BATCH   4
#define NTOK    16384
#define NHEADS  16
#define EPS     1e-6f
#define KCH     16

// ---------------- scratch ----------------
__device__ __half g_Xh[(size_t)NTOK * D_MODEL];
__device__ __half g_Ah[(size_t)NTOK * D_MODEL];
__device__ __half g_Qh[(size_t)NTOK * D_MODEL];
__device__ __half g_Kh[(size_t)NTOK * D_MODEL];
__device__ __half g_Vh[(size_t)NTOK * D_MODEL];
__device__ __half g_Wh[4][(size_t)D_MODEL * D_MODEL];   // transposed [n][k]
__device__ float  g_kvp[KCH * 64 * 4096];
__device__ float  g_ksp[KCH * 64 * 64];
__device__ float  g_kv[64 * 4096];
__device__ float  g_ks[64 * 64];

// ---------------- fp16 tensor-core GEMM ----------------
// C[M,1024] = A[M,1024](half) @ Bt[1024(n),1024(k)](half) + bias (+elu+1)
// Block 128x128, Ktile 32 halves, 256 thr = 8 warps (2x4), warp tile 64x32.
// 3-stage cp.async pipeline, 2 CTAs/SM. Smem rows 112B (conflict-free).
#define MATB   (128 * 112)             // 14336 bytes per matrix per stage
#define STAGEB (2 * MATB)              // 28672
#define NSTAGE 3
#define GEMM_SMEM (NSTAGE * STAGEB)    // 86016

__device__ __forceinline__ void cpasync16(uint32_t dst, const void* src) {
    asm volatile("cp.async.cg.shared.global [%0], [%1], 16;\n" ::"r"(dst), "l"(src));
}

__device__ __forceinline__ void load_tile(uint32_t sst, const __half* __restrict__ A,
                                          const __half* __restrict__ Bt,
                                          int m0, int n0, int kt, int tid) {
    const __half* Asrc = A + (size_t)m0 * 1024 + kt * 32;
    const __half* Bsrc = Bt + (size_t)n0 * 1024 + kt * 32;
#pragma unroll
    for (int j = 0; j < 2; j++) {
        int c = tid + j * 256;
        int row = c >> 2, kc = (c & 3) * 8;
        cpasync16(sst + (uint32_t)(row * 112 + kc * 2), Asrc + (size_t)row * 1024 + kc);
    }
#pragma unroll
    for (int j = 0; j < 2; j++) {
        int c = tid + j * 256;
        int row = c >> 2, kc = (c & 3) * 8;
        cpasync16(sst + (uint32_t)(MATB + row * 112 + kc * 2),
                  Bsrc + (size_t)row * 1024 + kc);
    }
    asm volatile("cp.async.commit_group;\n" ::: "memory");
}

template <int FMAP, typename OutT>
__global__ void __launch_bounds__(256, 2) gemm_h(const __half* __restrict__ A,
                                                 const __half* __restrict__ Bt,
                                                 const float* __restrict__ bias,
                                                 OutT* __restrict__ C) {
    extern __shared__ __align__(128) char smem[];
    uint32_t sb;
    asm("{ .reg .u64 t; cvta.to.shared.u64 t, %1; cvt.u32.u64 %0, t; }" : "=r"(sb) : "l"(smem));

    const int tid = threadIdx.x;
    const int lane = tid & 31, w = tid >> 5;
    const int wm = w & 1;
    const int wn = w >> 1;
    const int m0 = blockIdx.y * 128, n0 = blockIdx.x * 128;

    const uint32_t aOff = (uint32_t)((wm * 64 + (lane & 15)) * 112 + (lane >> 4) * 16);
    const uint32_t bOff = (uint32_t)(MATB + (wn * 32 + (lane >> 2)) * 112 + (lane & 3) * 4);

    float acc[4][4][4];
#pragma unroll
    for (int i = 0; i < 4; i++)
#pragma unroll
        for (int j = 0; j < 4; j++)
#pragma unroll
            for (int r = 0; r < 4; r++) acc[i][j][r] = 0.0f;

    load_tile(sb, A, Bt, m0, n0, 0, tid);
    load_tile(sb + STAGEB, A, Bt, m0, n0, 1, tid);

    int st = 0;
    for (int kt = 0; kt < 32; kt++) {
        if (kt < 31)
            asm volatile("cp.async.wait_group 1;\n" ::: "memory");
        else
            asm volatile("cp.async.wait_group 0;\n" ::: "memory");
        __syncthreads();
        if (kt + 2 < 32) {
            int nst = st + 2; if (nst >= NSTAGE) nst -= NSTAGE;
            load_tile(sb + (uint32_t)nst * STAGEB, A, Bt, m0, n0, kt + 2, tid);
        }
        const uint32_t cs = sb + (uint32_t)st * STAGEB;

#pragma unroll
        for (int ks = 0; ks < 2; ks++) {
            uint32_t a[4][4];
#pragma unroll
            for (int mf = 0; mf < 4; mf++) {
                uint32_t addr = cs + aOff + (uint32_t)(mf * 16 * 112 + ks * 32);
                asm volatile(
                    "ldmatrix.sync.aligned.m8n8.x4.shared.b16 {%0,%1,%2,%3}, [%4];"
                    : "=r"(a[mf][0]), "=r"(a[mf][1]), "=r"(a[mf][2]), "=r"(a[mf][3])
                    : "r"(addr));
            }
            uint32_t bf[4][2];
#pragma unroll
            for (int nf = 0; nf < 4; nf++) {
                uint32_t ba = cs + bOff + (uint32_t)(nf * 8 * 112 + ks * 32);
                asm volatile("ld.shared.b32 %0, [%1];" : "=r"(bf[nf][0]) : "r"(ba));
                asm volatile("ld.shared.b32 %0, [%1];" : "=r"(bf[nf][1]) : "r"(ba + 16));
            }
#pragma unroll
            for (int mf = 0; mf < 4; mf++)
#pragma unroll
                for (int nf = 0; nf < 4; nf++)
                    asm volatile(
                        "mma.sync.aligned.m16n8k16.row.col.f32.f16.f16.f32 "
                        "{%0,%1,%2,%3}, {%4,%5,%6,%7}, {%8,%9}, {%0,%1,%2,%3};"
                        : "+f"(acc[mf][nf][0]), "+f"(acc[mf][nf][1]),
                          "+f"(acc[mf][nf][2]), "+f"(acc[mf][nf][3])
                        : "r"(a[mf][0]), "r"(a[mf][1]), "r"(a[mf][2]), "r"(a[mf][3]),
                          "r"(bf[nf][0]), "r"(bf[nf][1]));
        }
        st++; if (st >= NSTAGE) st -= NSTAGE;
    }

    const int gr = lane >> 2, gc2 = (lane & 3) * 2;
#pragma unroll
    for (int mf = 0; mf < 4; mf++) {
        int r0 = m0 + wm * 64 + mf * 16 + gr;
#pragma unroll
        for (int nf = 0; nf < 4; nf++) {
            int col = n0 + wn * 32 + nf * 8 + gc2;
            float2 bb = *(const float2*)(bias + col);
            float v0 = acc[mf][nf][0] + bb.x;
            float v1 = acc[mf][nf][1] + bb.y;
            float v2 = acc[mf][nf][2] + bb.x;
            float v3 = acc[mf][nf][3] + bb.y;
            if (FMAP) {
                v0 = (v0 > 0.0f) ? v0 + 1.0f : expf(v0);
                v1 = (v1 > 0.0f) ? v1 + 1.0f : expf(v1);
                v2 = (v2 > 0.0f) ? v2 + 1.0f : expf(v2);
                v3 = (v3 > 0.0f) ? v3 + 1.0f : expf(v3);
            }
            if (sizeof(OutT) == 2) {
                __half2* p0 = (__half2*)((__half*)C + (size_t)r0 * 1024 + col);
                __half2* p1 = (__half2*)((__half*)C + (size_t)(r0 + 8) * 1024 + col);
                *p0 = __floats2half2_rn(v0, v1);
                *p1 = __floats2half2_rn(v2, v3);
            } else {
                float2 o0 = {v0, v1}, o1 = {v2, v3};
                *(float2*)((float*)C + (size_t)r0 * 1024 + col) = o0;
                *(float2*)((float*)C + (size_t)(r0 + 8) * 1024 + col) = o1;
            }
        }
    }
}

// ---------------- conversions ----------------
__global__ void to_half_kernel(const float4* __restrict__ in, __half2* __restrict__ out,
                               int n4) {
    int i = blockIdx.x * blockDim.x + threadIdx.x;
    if (i >= n4) return;
    float4 v = in[i];
    out[i * 2]     = __floats2half2_rn(v.x, v.y);
    out[i * 2 + 1] = __floats2half2_rn(v.z, v.w);
}

// Wt[n][k] = half(W[k][n]) for 4 matrices (z selects)
__global__ void transpose_half4(const float* __restrict__ W0, const float* __restrict__ W1,
                                const float* __restrict__ W2, const float* __restrict__ W3,
                                __half* __restrict__ Wt) {
    const float* W = (blockIdx.z == 0) ? W0 : (blockIdx.z == 1) ? W1
                     : (blockIdx.z == 2) ? W2 : W3;
    __half* Wo = Wt + (size_t)blockIdx.z * D_MODEL * D_MODEL;
    __shared__ float t[32][33];
    const int bx = blockIdx.x * 32, by = blockIdx.y * 32;
    const int tx = threadIdx.x, ty = threadIdx.y;
#pragma unroll
    for (int j = 0; j < 32; j += 8)
        t[ty + j][tx] = W[(size_t)(by + ty + j) * 1024 + bx + tx];
    __syncthreads();
#pragma unroll
    for (int j = 0; j < 32; j += 8)
        Wo[(size_t)(bx + ty + j) * 1024 + by + tx] = __float2half_rn(t[tx][ty + j]);
}

// ---------------- kv partial (half inputs) ----------------
__global__ __launch_bounds__(256) void kv_kernel(const __half* __restrict__ Kb,
                                                 const __half* __restrict__ Vb,
                                                 float* __restrict__ kvp,
                                                 float* __restrict__ ksp) {
    const int bh = blockIdx.x;
    const int ch = blockIdx.y;
    const int b = bh >> 4;
    const int h = bh & 15;

    __shared__ float Ks[32][64];
    __shared__ float Vs[32][64];

    const int tid = threadIdx.x;
    const int tx = tid & 15, ty = tid >> 4;
    const int d0 = ty * 4, e0 = tx * 4;

    float acc[4][4];
#pragma unroll
    for (int i = 0; i < 4; i++)
#pragma unroll
        for (int j = 0; j < 4; j++) acc[i][j] = 0.0f;
    float ks[4] = {0.f, 0.f, 0.f, 0.f};

    const __half* Kbase = Kb + (size_t)b * SEQ * D_MODEL + h * 64;
    const __half* Vbase = Vb + (size_t)b * SEQ * D_MODEL + h * 64;
    const int sBeg = ch * (SEQ / KCH);

    for (int s0 = sBeg; s0 < sBeg + SEQ / KCH; s0 += 32) {
        for (int i = tid; i < 512; i += 256) {
            int r = i >> 4, c4 = (i & 15) * 4;
            uint2 kr = *(const uint2*)(Kbase + (size_t)(s0 + r) * D_MODEL + c4);
            uint2 vr = *(const uint2*)(Vbase + (size_t)(s0 + r) * D_MODEL + c4);
            float2 k0 = __half22float2(*(__half2*)&kr.x);
            float2 k1 = __half22float2(*(__half2*)&kr.y);
            float2 v0 = __half22float2(*(__half2*)&vr.x);
            float2 v1 = __half22float2(*(__half2*)&vr.y);
            Ks[r][c4] = k0.x; Ks[r][c4 + 1] = k0.y; Ks[r][c4 + 2] = k1.x; Ks[r][c4 + 3] = k1.y;
            Vs[r][c4] = v0.x; Vs[r][c4 + 1] = v0.y; Vs[r][c4 + 2] = v1.x; Vs[r][c4 + 3] = v1.y;
        }
        __syncthreads();
#pragma unroll 8
        for (int s = 0; s < 32; s++) {
            float kd[4], ve[4];
            *(float4*)kd = *(float4*)&Ks[s][d0];
            *(float4*)ve = *(float4*)&Vs[s][e0];
#pragma unroll
            for (int i = 0; i < 4; i++)
#pragma unroll
                for (int j = 0; j < 4; j++) acc[i][j] = fmaf(kd[i], ve[j], acc[i][j]);
            if (tx == 0) {
#pragma unroll
                for (int i = 0; i < 4; i++) ks[i] += kd[i];
            }
        }
        __syncthreads();
    }

    float* kvo = kvp + ((size_t)ch * 64 + bh) * 4096;
#pragma unroll
    for (int i = 0; i < 4; i++) {
        float4 o = {acc[i][0], acc[i][1], acc[i][2], acc[i][3]};
        *(float4*)(kvo + (d0 + i) * 64 + e0) = o;
    }
    if (tx == 0)
#pragma unroll
        for (int i = 0; i < 4; i++) ksp[((size_t)ch * 64 + bh) * 64 + d0 + i] = ks[i];
}

__global__ void reduce_kernel(const float* __restrict__ kvp, const float* __restrict__ ksp,
                              float* __restrict__ kv, float* __restrict__ ks) {
    int i = blockIdx.x * 256 + threadIdx.x;
    if (i < 64 * 4096) {
        float s = 0.f;
#pragma unroll
        for (int c = 0; c < KCH; c++) s += kvp[(size_t)c * 64 * 4096 + i];
        kv[i] = s;
    }
    if (i < 64 * 64) {
        float s = 0.f;
#pragma unroll
        for (int c = 0; c < KCH; c++) s += ksp[(size_t)c * 64 * 64 + i];
        ks[i] = s;
    }
}

// ---------------- attention core (half q in, half out) ----------------
__global__ __launch_bounds__(256) void attn_kernel(const __half* __restrict__ Qb,
                                                   const float* __restrict__ kv,
                                                   const float* __restrict__ ksum,
                                                   __half* __restrict__ Ah) {
    const int bh = blockIdx.x;
    const int b = bh >> 4;
    const int h = bh & 15;
    const int s0 = blockIdx.y * 64;

    __shared__ float kvs[64][64];
    __shared__ float qs[64][64];
    __shared__ float kss[64];

    const int tid = threadIdx.x;
    {
        const float4* src = (const float4*)(kv + (size_t)bh * 4096);
        float4* dst = (float4*)&kvs[0][0];
        for (int i = tid; i < 1024; i += 256) dst[i] = src[i];
    }
    for (int i = tid; i < 64 * 16; i += 256) {
        int r = i >> 4, c4 = (i & 15) * 4;
        uint2 qr = *(const uint2*)(Qb + (size_t)(b * SEQ + s0 + r) * D_MODEL + h * 64 + c4);
        float2 q0 = __half22float2(*(__half2*)&qr.x);
        float2 q1 = __half22float2(*(__half2*)&qr.y);
        qs[r][c4] = q0.x; qs[r][c4 + 1] = q0.y; qs[r][c4 + 2] = q1.x; qs[r][c4 + 3] = q1.y;
    }
    if (tid < 16) ((float4*)kss)[tid] = ((const float4*)(ksum + bh * 64))[tid];
    __syncthreads();

    const int e = tid & 63;
    const int tsub = tid >> 6;
    for (int t = tsub; t < 64; t += 4) {
        float z = 0.0f, o = 0.0f;
#pragma unroll 16
        for (int d = 0; d < 64; d++) {
            float qd = qs[t][d];
            z = fmaf(qd, kss[d], z);
            o = fmaf(qd, kvs[d][e], o);
        }
        Ah[(size_t)(b * SEQ + s0 + t) * D_MODEL + h * 64 + e] = __float2half_rn(o / (z + EPS));
    }
}

// ---------------- launch ----------------
extern "C" void kernel_launch(void* const* d_in, const int* in_sizes, int n_in,
                              void* d_out, int out_size) {
    const float* x  = (const float*)d_in[0];
    const float* Wq = (const float*)d_in[1];
    const float* bq = (const float*)d_in[2];
    const float* Wk = (const float*)d_in[3];
    const float* bk = (const float*)d_in[4];
    const float* Wv = (const float*)d_in[5];
    const float* bv = (const float*)d_in[6];
    const float* Wo = (const float*)d_in[7];
    const float* bo = (const float*)d_in[8];
    float* out = (float*)d_out;

    __half *Xh, *Ah, *Qh, *Kh, *Vh, *Wh;
    float *kvp, *ksp, *kv, *ks;
    cudaGetSymbolAddress((void**)&Xh, g_Xh);
    cudaGetSymbolAddress((void**)&Ah, g_Ah);
    cudaGetSymbolAddress((void**)&Qh, g_Qh);
    cudaGetSymbolAddress((void**)&Kh, g_Kh);
    cudaGetSymbolAddress((void**)&Vh, g_Vh);
    cudaGetSymbolAddress((void**)&Wh, g_Wh);
    cudaGetSymbolAddress((void**)&kvp, g_kvp);
    cudaGetSymbolAddress((void**)&ksp, g_ksp);
    cudaGetSymbolAddress((void**)&kv, g_kv);
    cudaGetSymbolAddress((void**)&ks, g_ks);

    cudaFuncSetAttribute(gemm_h<0, __half>, cudaFuncAttributeMaxDynamicSharedMemorySize, GEMM_SMEM);
    cudaFuncSetAttribute(gemm_h<1, __half>, cudaFuncAttributeMaxDynamicSharedMemorySize, GEMM_SMEM);
    cudaFuncSetAttribute(gemm_h<0, float>, cudaFuncAttributeMaxDynamicSharedMemorySize, GEMM_SMEM);

    const size_t WN = (size_t)D_MODEL * D_MODEL;

    to_half_kernel<<<NTOK * D_MODEL / 4 / 256, 256>>>((const float4*)x, (__half2*)Xh,
                                                      NTOK * D_MODEL / 4);
    transpose_half4<<<dim3(32, 32, 4), dim3(32, 8)>>>(Wq, Wk, Wv, Wo, Wh);

    dim3 grid(8, 128);
    gemm_h<1, __half><<<grid, 256, GEMM_SMEM>>>(Xh, Wh + 0 * WN, bq, Qh);
    gemm_h<1, __half><<<grid, 256, GEMM_SMEM>>>(Xh, Wh + 1 * WN, bk, Kh);
    gemm_h<0, __half><<<grid, 256, GEMM_SMEM>>>(Xh, Wh + 2 * WN, bv, Vh);

    kv_kernel<<<dim3(64, KCH), 256>>>(Kh, Vh, kvp, ksp);
    reduce_kernel<<<(64 * 4096) / 256, 256>>>(kvp, ksp, kv, ks);
    attn_kernel<<<dim3(64, SEQ / 64), 256>>>(Qh, kv, ks, Ah);

    gemm_h<0, float><<<grid, 256, GEMM_SMEM>>>(Ah, Wh + 3 * WN, bo, out);
}

// round 6
// speedup vs baseline: 1.4398x; 1.4398x over previous
#include <cuda_runtime.h>
#include <cuda_fp16.h>
#include <math.h>
#include <stdint.h>

#define D_MODEL 1024
#define SEQ     4096
#define BATCH   4
#define NTOK    16384
#define NHEADS  16
#define EPS     1e-6f
#define KCH     8

// ---------------- scratch ----------------
__device__ __half g_Xh[(size_t)NTOK * D_MODEL];
__device__ __half g_Ah[(size_t)NTOK * D_MODEL];
__device__ __half g_Qh[(size_t)NTOK * D_MODEL];
__device__ __half g_Kh[(size_t)NTOK * D_MODEL];
__device__ __half g_Vh[(size_t)NTOK * D_MODEL];
__device__ __half g_Wh[4][(size_t)D_MODEL * D_MODEL];   // transposed [n][k]
__device__ float  g_kvp[KCH * 64 * 4096];
__device__ __half g_kvTh[64 * 4096];                    // kv^T per bh: [e][d]
__device__ float  g_ks[64 * 64];

// ---------------- fp16 tensor-core GEMM ----------------
// C[M,1024] = A[M,1024](half) @ Bt[1024(n),1024(k)](half) + bias (+elu+1)
// Block 128x128, Ktile 32 halves, 8 warps (2x4), warp tile 64x32.
// 3-stage cp.async, 2 CTAs/SM, A+B fragments both via ldmatrix.
#define MATB   (128 * 112)
#define STAGEB (2 * MATB)
#define NSTAGE 3
#define GEMM_SMEM (NSTAGE * STAGEB)

__device__ __forceinline__ void cpasync16(uint32_t dst, const void* src) {
    asm volatile("cp.async.cg.shared.global [%0], [%1], 16;\n" ::"r"(dst), "l"(src));
}

__device__ __forceinline__ void load_tile(uint32_t sst, const __half* __restrict__ A,
                                          const __half* __restrict__ Bt,
                                          int m0, int n0, int kt, int tid) {
    const __half* Asrc = A + (size_t)m0 * 1024 + kt * 32;
    const __half* Bsrc = Bt + (size_t)n0 * 1024 + kt * 32;
#pragma unroll
    for (int j = 0; j < 2; j++) {
        int c = tid + j * 256;
        int row = c >> 2, kc = (c & 3) * 8;
        cpasync16(sst + (uint32_t)(row * 112 + kc * 2), Asrc + (size_t)row * 1024 + kc);
    }
#pragma unroll
    for (int j = 0; j < 2; j++) {
        int c = tid + j * 256;
        int row = c >> 2, kc = (c & 3) * 8;
        cpasync16(sst + (uint32_t)(MATB + row * 112 + kc * 2),
                  Bsrc + (size_t)row * 1024 + kc);
    }
    asm volatile("cp.async.commit_group;\n" ::: "memory");
}

template <int FMAP, typename OutT>
__global__ void __launch_bounds__(256, 2) gemm_h(const __half* __restrict__ A,
                                                 const __half* __restrict__ Bt,
                                                 const float* __restrict__ bias,
                                                 OutT* __restrict__ C) {
    extern __shared__ __align__(128) char smem[];
    uint32_t sb;
    asm("{ .reg .u64 t; cvta.to.shared.u64 t, %1; cvt.u32.u64 %0, t; }" : "=r"(sb) : "l"(smem));

    const int tid = threadIdx.x;
    const int lane = tid & 31, w = tid >> 5;
    const int wm = w & 1;
    const int wn = w >> 1;
    const int m0 = blockIdx.y * 128, n0 = blockIdx.x * 128;

    const uint32_t aOff = (uint32_t)((wm * 64 + (lane & 15)) * 112 + (lane >> 4) * 16);
    // B ldmatrix: lanes0-7: n rows+r k0; 8-15: same n, k+8; 16-23: n+8 k0; 24-31: n+8 k+8
    const uint32_t bOff = (uint32_t)(MATB +
                                     (wn * 32 + ((lane >> 4) & 1) * 8 + (lane & 7)) * 112 +
                                     ((lane >> 3) & 1) * 16);

    float acc[4][4][4];
#pragma unroll
    for (int i = 0; i < 4; i++)
#pragma unroll
        for (int j = 0; j < 4; j++)
#pragma unroll
            for (int r = 0; r < 4; r++) acc[i][j][r] = 0.0f;

    load_tile(sb, A, Bt, m0, n0, 0, tid);
    load_tile(sb + STAGEB, A, Bt, m0, n0, 1, tid);

    int st = 0;
    for (int kt = 0; kt < 32; kt++) {
        if (kt < 31)
            asm volatile("cp.async.wait_group 1;\n" ::: "memory");
        else
            asm volatile("cp.async.wait_group 0;\n" ::: "memory");
        __syncthreads();
        if (kt + 2 < 32) {
            int nst = st + 2; if (nst >= NSTAGE) nst -= NSTAGE;
            load_tile(sb + (uint32_t)nst * STAGEB, A, Bt, m0, n0, kt + 2, tid);
        }
        const uint32_t cs = sb + (uint32_t)st * STAGEB;

#pragma unroll
        for (int ks = 0; ks < 2; ks++) {
            uint32_t a[4][4];
#pragma unroll
            for (int mf = 0; mf < 4; mf++) {
                uint32_t addr = cs + aOff + (uint32_t)(mf * 16 * 112 + ks * 32);
                asm volatile(
                    "ldmatrix.sync.aligned.m8n8.x4.shared.b16 {%0,%1,%2,%3}, [%4];"
                    : "=r"(a[mf][0]), "=r"(a[mf][1]), "=r"(a[mf][2]), "=r"(a[mf][3])
                    : "r"(addr));
            }
            uint32_t bf[4][2];
#pragma unroll
            for (int nfp = 0; nfp < 2; nfp++) {
                uint32_t addr = cs + bOff + (uint32_t)(nfp * 16 * 112 + ks * 32);
                asm volatile(
                    "ldmatrix.sync.aligned.m8n8.x4.shared.b16 {%0,%1,%2,%3}, [%4];"
                    : "=r"(bf[nfp * 2][0]), "=r"(bf[nfp * 2][1]),
                      "=r"(bf[nfp * 2 + 1][0]), "=r"(bf[nfp * 2 + 1][1])
                    : "r"(addr));
            }
#pragma unroll
            for (int mf = 0; mf < 4; mf++)
#pragma unroll
                for (int nf = 0; nf < 4; nf++)
                    asm volatile(
                        "mma.sync.aligned.m16n8k16.row.col.f32.f16.f16.f32 "
                        "{%0,%1,%2,%3}, {%4,%5,%6,%7}, {%8,%9}, {%0,%1,%2,%3};"
                        : "+f"(acc[mf][nf][0]), "+f"(acc[mf][nf][1]),
                          "+f"(acc[mf][nf][2]), "+f"(acc[mf][nf][3])
                        : "r"(a[mf][0]), "r"(a[mf][1]), "r"(a[mf][2]), "r"(a[mf][3]),
                          "r"(bf[nf][0]), "r"(bf[nf][1]));
        }
        st++; if (st >= NSTAGE) st -= NSTAGE;
    }

    const int gr = lane >> 2, gc2 = (lane & 3) * 2;
#pragma unroll
    for (int mf = 0; mf < 4; mf++) {
        int r0 = m0 + wm * 64 + mf * 16 + gr;
#pragma unroll
        for (int nf = 0; nf < 4; nf++) {
            int col = n0 + wn * 32 + nf * 8 + gc2;
            float2 bb = *(const float2*)(bias + col);
            float v0 = acc[mf][nf][0] + bb.x;
            float v1 = acc[mf][nf][1] + bb.y;
            float v2 = acc[mf][nf][2] + bb.x;
            float v3 = acc[mf][nf][3] + bb.y;
            if (FMAP) {
                v0 = (v0 > 0.0f) ? v0 + 1.0f : expf(v0);
                v1 = (v1 > 0.0f) ? v1 + 1.0f : expf(v1);
                v2 = (v2 > 0.0f) ? v2 + 1.0f : expf(v2);
                v3 = (v3 > 0.0f) ? v3 + 1.0f : expf(v3);
            }
            if (sizeof(OutT) == 2) {
                *(__half2*)((__half*)C + (size_t)r0 * 1024 + col) = __floats2half2_rn(v0, v1);
                *(__half2*)((__half*)C + (size_t)(r0 + 8) * 1024 + col) = __floats2half2_rn(v2, v3);
            } else {
                float2 o0 = {v0, v1}, o1 = {v2, v3};
                *(float2*)((float*)C + (size_t)r0 * 1024 + col) = o0;
                *(float2*)((float*)C + (size_t)(r0 + 8) * 1024 + col) = o1;
            }
        }
    }
}

// ---------------- conversions ----------------
__global__ void to_half_kernel(const float4* __restrict__ in, __half2* __restrict__ out,
                               int n4) {
    int i = blockIdx.x * blockDim.x + threadIdx.x;
    if (i >= n4) return;
    float4 v = in[i];
    out[i * 2]     = __floats2half2_rn(v.x, v.y);
    out[i * 2 + 1] = __floats2half2_rn(v.z, v.w);
}

__global__ void transpose_half4(const float* __restrict__ W0, const float* __restrict__ W1,
                                const float* __restrict__ W2, const float* __restrict__ W3,
                                __half* __restrict__ Wt) {
    const float* W = (blockIdx.z == 0) ? W0 : (blockIdx.z == 1) ? W1
                     : (blockIdx.z == 2) ? W2 : W3;
    __half* Wo = Wt + (size_t)blockIdx.z * D_MODEL * D_MODEL;
    __shared__ float t[32][33];
    const int bx = blockIdx.x * 32, by = blockIdx.y * 32;
    const int tx = threadIdx.x, ty = threadIdx.y;
#pragma unroll
    for (int j = 0; j < 32; j += 8)
        t[ty + j][tx] = W[(size_t)(by + ty + j) * 1024 + bx + tx];
    __syncthreads();
#pragma unroll
    for (int j = 0; j < 32; j += 8)
        Wo[(size_t)(bx + ty + j) * 1024 + by + tx] = __float2half_rn(t[tx][ty + j]);
}

// ---------------- kv via tensor cores: kvp[ch][bh] = K_chunk^T @ V_chunk --------
// Contraction over s (stored rows) -> ldmatrix.trans for both operands.
#define KVST 72   // smem row stride in halves (144B, conflict-free for ldmatrix)
__global__ void __launch_bounds__(128) kv_tc(const __half* __restrict__ Kh,
                                             const __half* __restrict__ Vh,
                                             float* __restrict__ kvp) {
    const int bh = blockIdx.x, ch = blockIdx.y;
    const int b = bh >> 4, h = bh & 15;
    __shared__ __half Ks[64 * KVST];
    __shared__ __half Vs[64 * KVST];

    const int tid = threadIdx.x;
    const int lane = tid & 31, w = tid >> 5;
    const int d0 = w * 16;
    const int g = lane >> 3, r = lane & 7;

    uint32_t ksb, vsb;
    asm("{ .reg .u64 t; cvta.to.shared.u64 t, %1; cvt.u32.u64 %0, t; }" : "=r"(ksb) : "l"(Ks));
    asm("{ .reg .u64 t; cvta.to.shared.u64 t, %1; cvt.u32.u64 %0, t; }" : "=r"(vsb) : "l"(Vs));

    // A (K^T) trans-ldmatrix lane pattern: sRow = ((g>>1)&1)*8 + r, col = d0 + (g&1)*8
    const uint32_t aLane = (uint32_t)(((((g >> 1) & 1) * 8 + r) * KVST + d0 + (g & 1) * 8) * 2);
    // B (V) trans-ldmatrix: sRow = (g&1)*8 + r, col = (g>>1)*8  (+ e0 per call)
    const uint32_t bLane = (uint32_t)((((g & 1) * 8 + r) * KVST + ((g >> 1) & 1) * 8) * 2);

    float acc[8][4];
#pragma unroll
    for (int i = 0; i < 8; i++)
#pragma unroll
        for (int j = 0; j < 4; j++) acc[i][j] = 0.0f;

    const __half* Kbase = Kh + (size_t)b * SEQ * D_MODEL + h * 64;
    const __half* Vbase = Vh + (size_t)b * SEQ * D_MODEL + h * 64;
    const int sBeg = ch * (SEQ / KCH);

    for (int t = 0; t < (SEQ / KCH) / 64; t++) {
        for (int j = 0; j < 4; j++) {
            int c = tid + j * 128;                 // 512 chunks of 16B
            int row = c >> 3, col8 = (c & 7) * 8;
            const size_t gidx = (size_t)(sBeg + t * 64 + row) * 1024 + col8;
            *(uint4*)&Ks[row * KVST + col8] = *(const uint4*)(Kbase + gidx);
            *(uint4*)&Vs[row * KVST + col8] = *(const uint4*)(Vbase + gidx);
        }
        __syncthreads();

#pragma unroll
        for (int kk = 0; kk < 4; kk++) {
            uint32_t a[4];
            uint32_t aaddr = ksb + aLane + (uint32_t)(kk * 16 * KVST * 2);
            asm volatile(
                "ldmatrix.sync.aligned.m8n8.x4.trans.shared.b16 {%0,%1,%2,%3}, [%4];"
                : "=r"(a[0]), "=r"(a[1]), "=r"(a[2]), "=r"(a[3]) : "r"(aaddr));
            uint32_t bf[8][2];
#pragma unroll
            for (int nfp = 0; nfp < 4; nfp++) {
                uint32_t baddr = vsb + bLane + (uint32_t)((kk * 16 * KVST + nfp * 16) * 2);
                asm volatile(
                    "ldmatrix.sync.aligned.m8n8.x4.trans.shared.b16 {%0,%1,%2,%3}, [%4];"
                    : "=r"(bf[nfp * 2][0]), "=r"(bf[nfp * 2][1]),
                      "=r"(bf[nfp * 2 + 1][0]), "=r"(bf[nfp * 2 + 1][1])
                    : "r"(baddr));
            }
#pragma unroll
            for (int nf = 0; nf < 8; nf++)
                asm volatile(
                    "mma.sync.aligned.m16n8k16.row.col.f32.f16.f16.f32 "
                    "{%0,%1,%2,%3}, {%4,%5,%6,%7}, {%8,%9}, {%0,%1,%2,%3};"
                    : "+f"(acc[nf][0]), "+f"(acc[nf][1]), "+f"(acc[nf][2]), "+f"(acc[nf][3])
                    : "r"(a[0]), "r"(a[1]), "r"(a[2]), "r"(a[3]),
                      "r"(bf[nf][0]), "r"(bf[nf][1]));
        }
        __syncthreads();
    }

    float* kvo = kvp + ((size_t)ch * 64 + bh) * 4096;
    const int gr = lane >> 2, gc2 = (lane & 3) * 2;
#pragma unroll
    for (int nf = 0; nf < 8; nf++) {
        int col = nf * 8 + gc2;
        *(float2*)(kvo + (d0 + gr) * 64 + col) = make_float2(acc[nf][0], acc[nf][1]);
        *(float2*)(kvo + (d0 + gr + 8) * 64 + col) = make_float2(acc[nf][2], acc[nf][3]);
    }
}

// ---------------- reduce kv partials -> kv^T in fp16 ----------------
__global__ void reduce_kv(const float* __restrict__ kvp, __half* __restrict__ kvTh) {
    int i = blockIdx.x * 256 + threadIdx.x;   // over 64*4096
    int bh = i >> 12, idx = i & 4095;
    int d = idx >> 6, e = idx & 63;
    float s = 0.f;
#pragma unroll
    for (int c = 0; c < KCH; c++) s += kvp[((size_t)c * 64 + bh) * 4096 + idx];
    kvTh[(size_t)bh * 4096 + e * 64 + d] = __float2half_rn(s);
}

// ---------------- ksum: ks[bh][d] = sum_s K ----------------
__global__ void __launch_bounds__(256) ksum_kernel(const __half* __restrict__ Kh,
                                                   float* __restrict__ ks) {
    const int bh = blockIdx.x;
    const int b = bh >> 4, h = bh & 15;
    const int d = threadIdx.x & 63, sl = threadIdx.x >> 6;
    const __half* Kbase = Kh + (size_t)b * SEQ * D_MODEL + h * 64 + d;
    float s = 0.f;
    for (int ss = sl; ss < SEQ; ss += 4) s += __half2float(Kbase[(size_t)ss * D_MODEL]);
    __shared__ float red[256];
    red[threadIdx.x] = s;
    __syncthreads();
    if (threadIdx.x < 64)
        ks[bh * 64 + d] = red[d] + red[d + 64] + red[d + 128] + red[d + 192];
}

// ---------------- attention core via tensor cores ----------------
// out[s][e] = (q[s][:] @ kv[:,e]) / (q . ksum + eps); A=q (plain), B=kv^T (plain)
__global__ void __launch_bounds__(128) attn_tc(const __half* __restrict__ Qh,
                                               const __half* __restrict__ kvTh,
                                               const float* __restrict__ ksum,
                                               __half* __restrict__ Ah) {
    const int bh = blockIdx.x;
    const int b = bh >> 4, h = bh & 15;
    const int s0 = blockIdx.y * 64;
    __shared__ __half qs[64 * KVST];
    __shared__ __half kvs[64 * KVST];
    __shared__ float kss[64];

    const int tid = threadIdx.x;
    const int lane = tid & 31, w = tid >> 5;
    const int m0w = w * 16;

    uint32_t qsb, kvb;
    asm("{ .reg .u64 t; cvta.to.shared.u64 t, %1; cvt.u32.u64 %0, t; }" : "=r"(qsb) : "l"(qs));
    asm("{ .reg .u64 t; cvta.to.shared.u64 t, %1; cvt.u32.u64 %0, t; }" : "=r"(kvb) : "l"(kvs));

    for (int j = 0; j < 4; j++) {
        int c = tid + j * 128;
        int row = c >> 3, col8 = (c & 7) * 8;
        *(uint4*)&qs[row * KVST + col8] =
            *(const uint4*)(Qh + (size_t)(b * SEQ + s0 + row) * 1024 + h * 64 + col8);
        *(uint4*)&kvs[row * KVST + col8] =
            *(const uint4*)(kvTh + (size_t)bh * 4096 + row * 64 + col8);
    }
    if (tid < 64) kss[tid] = ksum[bh * 64 + tid];
    __syncthreads();

    // A: rows m0w + (lane&15), col (lane>>4)*8
    const uint32_t aLane = (uint32_t)(((m0w + (lane & 15)) * KVST + (lane >> 4) * 8) * 2);
    // B: rows e = ((lane>>4)&1)*8 + (lane&7)  (+nfp*16), col ((lane>>3)&1)*8 (+kk*16)
    const uint32_t bLane = (uint32_t)(((((lane >> 4) & 1) * 8 + (lane & 7)) * KVST +
                                       ((lane >> 3) & 1) * 8) * 2);

    float acc[8][4];
#pragma unroll
    for (int i = 0; i < 8; i++)
#pragma unroll
        for (int j = 0; j < 4; j++) acc[i][j] = 0.0f;

#pragma unroll
    for (int kk = 0; kk < 4; kk++) {
        uint32_t a[4];
        uint32_t aaddr = qsb + aLane + (uint32_t)(kk * 32);
        asm volatile(
            "ldmatrix.sync.aligned.m8n8.x4.shared.b16 {%0,%1,%2,%3}, [%4];"
            : "=r"(a[0]), "=r"(a[1]), "=r"(a[2]), "=r"(a[3]) : "r"(aaddr));
        uint32_t bf[8][2];
#pragma unroll
        for (int nfp = 0; nfp < 4; nfp++) {
            uint32_t baddr = kvb + bLane + (uint32_t)((nfp * 16 * KVST + kk * 16) * 2);
            asm volatile(
                "ldmatrix.sync.aligned.m8n8.x4.shared.b16 {%0,%1,%2,%3}, [%4];"
                : "=r"(bf[nfp * 2][0]), "=r"(bf[nfp * 2][1]),
                  "=r"(bf[nfp * 2 + 1][0]), "=r"(bf[nfp * 2 + 1][1])
                : "r"(baddr));
        }
#pragma unroll
        for (int nf = 0; nf < 8; nf++)
            asm volatile(
                "mma.sync.aligned.m16n8k16.row.col.f32.f16.f16.f32 "
                "{%0,%1,%2,%3}, {%4,%5,%6,%7}, {%8,%9}, {%0,%1,%2,%3};"
                : "+f"(acc[nf][0]), "+f"(acc[nf][1]), "+f"(acc[nf][2]), "+f"(acc[nf][3])
                : "r"(a[0]), "r"(a[1]), "r"(a[2]), "r"(a[3]),
                  "r"(bf[nf][0]), "r"(bf[nf][1]));
    }

    // z in fp32 for this lane's two rows
    const int gr = lane >> 2, gc2 = (lane & 3) * 2;
    float z0 = 0.f, z1 = 0.f;
#pragma unroll 8
    for (int d = 0; d < 64; d++) {
        float kd = kss[d];
        z0 = fmaf(__half2float(qs[(m0w + gr) * KVST + d]), kd, z0);
        z1 = fmaf(__half2float(qs[(m0w + gr + 8) * KVST + d]), kd, z1);
    }
    const float iz0 = 1.0f / (z0 + EPS), iz1 = 1.0f / (z1 + EPS);

    __half* Aout = Ah + (size_t)(b * SEQ + s0 + m0w) * 1024 + h * 64;
#pragma unroll
    for (int nf = 0; nf < 8; nf++) {
        int col = nf * 8 + gc2;
        *(__half2*)(Aout + (size_t)gr * 1024 + col) =
            __floats2half2_rn(acc[nf][0] * iz0, acc[nf][1] * iz0);
        *(__half2*)(Aout + (size_t)(gr + 8) * 1024 + col) =
            __floats2half2_rn(acc[nf][2] * iz1, acc[nf][3] * iz1);
    }
}

// ---------------- launch ----------------
extern "C" void kernel_launch(void* const* d_in, const int* in_sizes, int n_in,
                              void* d_out, int out_size) {
    const float* x  = (const float*)d_in[0];
    const float* Wq = (const float*)d_in[1];
    const float* bq = (const float*)d_in[2];
    const float* Wk = (const float*)d_in[3];
    const float* bk = (const float*)d_in[4];
    const float* Wv = (const float*)d_in[5];
    const float* bv = (const float*)d_in[6];
    const float* Wo = (const float*)d_in[7];
    const float* bo = (const float*)d_in[8];
    float* out = (float*)d_out;

    __half *Xh, *Ah, *Qh, *Kh, *Vh, *Wh, *kvTh;
    float *kvp, *ks;
    cudaGetSymbolAddress((void**)&Xh, g_Xh);
    cudaGetSymbolAddress((void**)&Ah, g_Ah);
    cudaGetSymbolAddress((void**)&Qh, g_Qh);
    cudaGetSymbolAddress((void**)&Kh, g_Kh);
    cudaGetSymbolAddress((void**)&Vh, g_Vh);
    cudaGetSymbolAddress((void**)&Wh, g_Wh);
    cudaGetSymbolAddress((void**)&kvp, g_kvp);
    cudaGetSymbolAddress((void**)&kvTh, g_kvTh);
    cudaGetSymbolAddress((void**)&ks, g_ks);

    cudaFuncSetAttribute(gemm_h<0, __half>, cudaFuncAttributeMaxDynamicSharedMemorySize, GEMM_SMEM);
    cudaFuncSetAttribute(gemm_h<1, __half>, cudaFuncAttributeMaxDynamicSharedMemorySize, GEMM_SMEM);
    cudaFuncSetAttribute(gemm_h<0, float>, cudaFuncAttributeMaxDynamicSharedMemorySize, GEMM_SMEM);

    const size_t WN = (size_t)D_MODEL * D_MODEL;

    to_half_kernel<<<NTOK * D_MODEL / 4 / 256, 256>>>((const float4*)x, (__half2*)Xh,
                                                      NTOK * D_MODEL / 4);
    transpose_half4<<<dim3(32, 32, 4), dim3(32, 8)>>>(Wq, Wk, Wv, Wo, Wh);

    dim3 grid(8, 128);
    gemm_h<1, __half><<<grid, 256, GEMM_SMEM>>>(Xh, Wh + 0 * WN, bq, Qh);
    gemm_h<1, __half><<<grid, 256, GEMM_SMEM>>>(Xh, Wh + 1 * WN, bk, Kh);
    gemm_h<0, __half><<<grid, 256, GEMM_SMEM>>>(Xh, Wh + 2 * WN, bv, Vh);

    kv_tc<<<dim3(64, KCH), 128>>>(Kh, Vh, kvp);
    reduce_kv<<<(64 * 4096) / 256, 256>>>(kvp, kvTh);
    ksum_kernel<<<64, 256>>>(Kh, ks);
    attn_tc<<<dim3(64, SEQ / 64), 128>>>(Qh, kvTh, ks, Ah);

    gemm_h<0, float><<<grid, 256, GEMM_SMEM>>>(Ah, Wh + 3 * WN, bo, out);
}

// round 7
// speedup vs baseline: 1.5331x; 1.0648x over previous
#include <cuda_runtime.h>
#include <cuda_fp16.h>
#include <math.h>
#include <stdint.h>

#define D_MODEL 1024
#define SEQ     4096
#define BATCH   4
#define NTOK    16384
#define NHEADS  16
#define EPS     1e-6f
#define KCH     8

// ---------------- scratch ----------------
__device__ __half g_Xh[(size_t)NTOK * D_MODEL];
__device__ __half g_Ah[(size_t)NTOK * D_MODEL];
__device__ __half g_Qh[(size_t)NTOK * D_MODEL];
__device__ __half g_Kh[(size_t)NTOK * D_MODEL];
__device__ __half g_Vh[(size_t)NTOK * D_MODEL];
__device__ __half g_Wh[4][(size_t)D_MODEL * D_MODEL];   // transposed [n][k]
__device__ float  g_bqkv[3 * D_MODEL];
__device__ float  g_kvp[KCH * 64 * 4096];
__device__ __half g_kvTh[64 * 4096];                    // kv^T per bh: [e][d]
__device__ float  g_ks[64 * 64];

// ---------------- fp16 tensor-core GEMM, warp tile 64x64 ----------------
// Block 128x128, 128 threads = 4 warps (2x2), Ktile 32 halves, 3-stage cp.async,
// 2 CTAs/SM. FUSED=1: N spans 3072 (Q|K|V), output/bias/fmap selected by n0.
#define MATB   (128 * 112)
#define STAGEB (2 * MATB)
#define NSTAGE 3
#define GEMM_SMEM (NSTAGE * STAGEB)

__device__ __forceinline__ void cpasync16(uint32_t dst, const void* src) {
    asm volatile("cp.async.cg.shared.global [%0], [%1], 16;\n" ::"r"(dst), "l"(src));
}

__device__ __forceinline__ void load_tile(uint32_t sst, const __half* __restrict__ A,
                                          const __half* __restrict__ Bt,
                                          int m0, int n0, int kt, int tid) {
    const __half* Asrc = A + (size_t)m0 * 1024 + kt * 32;
    const __half* Bsrc = Bt + (size_t)n0 * 1024 + kt * 32;
#pragma unroll
    for (int j = 0; j < 4; j++) {
        int c = tid + j * 128;
        int row = c >> 2, kc = (c & 3) * 8;
        cpasync16(sst + (uint32_t)(row * 112 + kc * 2), Asrc + (size_t)row * 1024 + kc);
    }
#pragma unroll
    for (int j = 0; j < 4; j++) {
        int c = tid + j * 128;
        int row = c >> 2, kc = (c & 3) * 8;
        cpasync16(sst + (uint32_t)(MATB + row * 112 + kc * 2),
                  Bsrc + (size_t)row * 1024 + kc);
    }
    asm volatile("cp.async.commit_group;\n" ::: "memory");
}

template <int FUSED, typename OutT>
__global__ void __launch_bounds__(128, 2) gemm_wt64(const __half* __restrict__ A,
                                                    const __half* __restrict__ Bt,
                                                    const float* __restrict__ bias,
                                                    OutT* __restrict__ C0,
                                                    OutT* __restrict__ C1,
                                                    OutT* __restrict__ C2) {
    extern __shared__ __align__(128) char smem[];
    uint32_t sb;
    asm("{ .reg .u64 t; cvta.to.shared.u64 t, %1; cvt.u32.u64 %0, t; }" : "=r"(sb) : "l"(smem));

    const int tid = threadIdx.x;
    const int lane = tid & 31, w = tid >> 5;
    const int wm = w & 1;        // m offset *64
    const int wn = w >> 1;       // n offset *64
    const int m0 = blockIdx.y * 128, n0 = blockIdx.x * 128;

    const uint32_t aOff = (uint32_t)((wm * 64 + (lane & 15)) * 112 + (lane >> 4) * 16);
    const uint32_t bOff = (uint32_t)(MATB +
                                     (wn * 64 + ((lane >> 4) & 1) * 8 + (lane & 7)) * 112 +
                                     ((lane >> 3) & 1) * 16);

    float acc[4][8][4];
#pragma unroll
    for (int i = 0; i < 4; i++)
#pragma unroll
        for (int j = 0; j < 8; j++)
#pragma unroll
            for (int r = 0; r < 4; r++) acc[i][j][r] = 0.0f;

    load_tile(sb, A, Bt, m0, n0, 0, tid);
    load_tile(sb + STAGEB, A, Bt, m0, n0, 1, tid);

    int st = 0;
    for (int kt = 0; kt < 32; kt++) {
        if (kt < 31)
            asm volatile("cp.async.wait_group 1;\n" ::: "memory");
        else
            asm volatile("cp.async.wait_group 0;\n" ::: "memory");
        __syncthreads();
        if (kt + 2 < 32) {
            int nst = st + 2; if (nst >= NSTAGE) nst -= NSTAGE;
            load_tile(sb + (uint32_t)nst * STAGEB, A, Bt, m0, n0, kt + 2, tid);
        }
        const uint32_t cs = sb + (uint32_t)st * STAGEB;

#pragma unroll
        for (int ks = 0; ks < 2; ks++) {
            uint32_t a[4][4];
#pragma unroll
            for (int mf = 0; mf < 4; mf++) {
                uint32_t addr = cs + aOff + (uint32_t)(mf * 16 * 112 + ks * 32);
                asm volatile(
                    "ldmatrix.sync.aligned.m8n8.x4.shared.b16 {%0,%1,%2,%3}, [%4];"
                    : "=r"(a[mf][0]), "=r"(a[mf][1]), "=r"(a[mf][2]), "=r"(a[mf][3])
                    : "r"(addr));
            }
#pragma unroll
            for (int nfp = 0; nfp < 4; nfp++) {
                uint32_t b0, b1, b2, b3;
                uint32_t addr = cs + bOff + (uint32_t)(nfp * 16 * 112 + ks * 32);
                asm volatile(
                    "ldmatrix.sync.aligned.m8n8.x4.shared.b16 {%0,%1,%2,%3}, [%4];"
                    : "=r"(b0), "=r"(b1), "=r"(b2), "=r"(b3) : "r"(addr));
#pragma unroll
                for (int mf = 0; mf < 4; mf++) {
                    asm volatile(
                        "mma.sync.aligned.m16n8k16.row.col.f32.f16.f16.f32 "
                        "{%0,%1,%2,%3}, {%4,%5,%6,%7}, {%8,%9}, {%0,%1,%2,%3};"
                        : "+f"(acc[mf][nfp * 2][0]), "+f"(acc[mf][nfp * 2][1]),
                          "+f"(acc[mf][nfp * 2][2]), "+f"(acc[mf][nfp * 2][3])
                        : "r"(a[mf][0]), "r"(a[mf][1]), "r"(a[mf][2]), "r"(a[mf][3]),
                          "r"(b0), "r"(b1));
                    asm volatile(
                        "mma.sync.aligned.m16n8k16.row.col.f32.f16.f16.f32 "
                        "{%0,%1,%2,%3}, {%4,%5,%6,%7}, {%8,%9}, {%0,%1,%2,%3};"
                        : "+f"(acc[mf][nfp * 2 + 1][0]), "+f"(acc[mf][nfp * 2 + 1][1]),
                          "+f"(acc[mf][nfp * 2 + 1][2]), "+f"(acc[mf][nfp * 2 + 1][3])
                        : "r"(a[mf][0]), "r"(a[mf][1]), "r"(a[mf][2]), "r"(a[mf][3]),
                          "r"(b2), "r"(b3));
                }
            }
        }
        st++; if (st >= NSTAGE) st -= NSTAGE;
    }

    // output selection
    OutT* C = C0;
    int ncol0 = n0;
    bool fmap = false;
    if (FUSED) {
        if (n0 < 1024)      { C = C0; ncol0 = n0;        fmap = true; }
        else if (n0 < 2048) { C = C1; ncol0 = n0 - 1024; fmap = true; }
        else                { C = C2; ncol0 = n0 - 2048; fmap = false; }
    }

    const int gr = lane >> 2, gc2 = (lane & 3) * 2;
#pragma unroll
    for (int mf = 0; mf < 4; mf++) {
        int r0 = m0 + wm * 64 + mf * 16 + gr;
#pragma unroll
        for (int nf = 0; nf < 8; nf++) {
            int colg = n0 + wn * 64 + nf * 8 + gc2;          // global bias index
            int col = ncol0 + wn * 64 + nf * 8 + gc2;        // output col
            float2 bb = *(const float2*)(bias + colg);
            float v0 = acc[mf][nf][0] + bb.x;
            float v1 = acc[mf][nf][1] + bb.y;
            float v2 = acc[mf][nf][2] + bb.x;
            float v3 = acc[mf][nf][3] + bb.y;
            if (FUSED && fmap) {
                v0 = (v0 > 0.0f) ? v0 + 1.0f : expf(v0);
                v1 = (v1 > 0.0f) ? v1 + 1.0f : expf(v1);
                v2 = (v2 > 0.0f) ? v2 + 1.0f : expf(v2);
                v3 = (v3 > 0.0f) ? v3 + 1.0f : expf(v3);
            }
            if (sizeof(OutT) == 2) {
                *(__half2*)((__half*)C + (size_t)r0 * 1024 + col) = __floats2half2_rn(v0, v1);
                *(__half2*)((__half*)C + (size_t)(r0 + 8) * 1024 + col) = __floats2half2_rn(v2, v3);
            } else {
                float2 o0 = {v0, v1}, o1 = {v2, v3};
                *(float2*)((float*)C + (size_t)r0 * 1024 + col) = o0;
                *(float2*)((float*)C + (size_t)(r0 + 8) * 1024 + col) = o1;
            }
        }
    }
}

// ---------------- conversions ----------------
__global__ void to_half_kernel(const float4* __restrict__ in, __half2* __restrict__ out,
                               int n4) {
    int i = blockIdx.x * blockDim.x + threadIdx.x;
    if (i >= n4) return;
    float4 v = in[i];
    out[i * 2]     = __floats2half2_rn(v.x, v.y);
    out[i * 2 + 1] = __floats2half2_rn(v.z, v.w);
}

__global__ void transpose_half4(const float* __restrict__ W0, const float* __restrict__ W1,
                                const float* __restrict__ W2, const float* __restrict__ W3,
                                __half* __restrict__ Wt) {
    const float* W = (blockIdx.z == 0) ? W0 : (blockIdx.z == 1) ? W1
                     : (blockIdx.z == 2) ? W2 : W3;
    __half* Wo = Wt + (size_t)blockIdx.z * D_MODEL * D_MODEL;
    __shared__ float t[32][33];
    const int bx = blockIdx.x * 32, by = blockIdx.y * 32;
    const int tx = threadIdx.x, ty = threadIdx.y;
#pragma unroll
    for (int j = 0; j < 32; j += 8)
        t[ty + j][tx] = W[(size_t)(by + ty + j) * 1024 + bx + tx];
    __syncthreads();
#pragma unroll
    for (int j = 0; j < 32; j += 8)
        Wo[(size_t)(bx + ty + j) * 1024 + by + tx] = __float2half_rn(t[tx][ty + j]);
}

__global__ void pack_bias(const float* __restrict__ bq, const float* __restrict__ bk,
                          const float* __restrict__ bv, float* __restrict__ o) {
    int i = blockIdx.x * 256 + threadIdx.x;
    if (i < 1024) o[i] = bq[i];
    else if (i < 2048) o[i] = bk[i - 1024];
    else if (i < 3072) o[i] = bv[i - 2048];
}

// ---------------- kv via tensor cores ----------------
#define KVST 72
__global__ void __launch_bounds__(128) kv_tc(const __half* __restrict__ Kh,
                                             const __half* __restrict__ Vh,
                                             float* __restrict__ kvp) {
    const int bh = blockIdx.x, ch = blockIdx.y;
    const int b = bh >> 4, h = bh & 15;
    __shared__ __half Ks[64 * KVST];
    __shared__ __half Vs[64 * KVST];

    const int tid = threadIdx.x;
    const int lane = tid & 31, w = tid >> 5;
    const int d0 = w * 16;
    const int g = lane >> 3, r = lane & 7;

    uint32_t ksb, vsb;
    asm("{ .reg .u64 t; cvta.to.shared.u64 t, %1; cvt.u32.u64 %0, t; }" : "=r"(ksb) : "l"(Ks));
    asm("{ .reg .u64 t; cvta.to.shared.u64 t, %1; cvt.u32.u64 %0, t; }" : "=r"(vsb) : "l"(Vs));

    const uint32_t aLane = (uint32_t)(((((g >> 1) & 1) * 8 + r) * KVST + d0 + (g & 1) * 8) * 2);
    const uint32_t bLane = (uint32_t)((((g & 1) * 8 + r) * KVST + ((g >> 1) & 1) * 8) * 2);

    float acc[8][4];
#pragma unroll
    for (int i = 0; i < 8; i++)
#pragma unroll
        for (int j = 0; j < 4; j++) acc[i][j] = 0.0f;

    const __half* Kbase = Kh + (size_t)b * SEQ * D_MODEL + h * 64;
    const __half* Vbase = Vh + (size_t)b * SEQ * D_MODEL + h * 64;
    const int sBeg = ch * (SEQ / KCH);

    for (int t = 0; t < (SEQ / KCH) / 64; t++) {
        for (int j = 0; j < 4; j++) {
            int c = tid + j * 128;
            int row = c >> 3, col8 = (c & 7) * 8;
            const size_t gidx = (size_t)(sBeg + t * 64 + row) * 1024 + col8;
            *(uint4*)&Ks[row * KVST + col8] = *(const uint4*)(Kbase + gidx);
            *(uint4*)&Vs[row * KVST + col8] = *(const uint4*)(Vbase + gidx);
        }
        __syncthreads();

#pragma unroll
        for (int kk = 0; kk < 4; kk++) {
            uint32_t a[4];
            uint32_t aaddr = ksb + aLane + (uint32_t)(kk * 16 * KVST * 2);
            asm volatile(
                "ldmatrix.sync.aligned.m8n8.x4.trans.shared.b16 {%0,%1,%2,%3}, [%4];"
                : "=r"(a[0]), "=r"(a[1]), "=r"(a[2]), "=r"(a[3]) : "r"(aaddr));
            uint32_t bf[8][2];
#pragma unroll
            for (int nfp = 0; nfp < 4; nfp++) {
                uint32_t baddr = vsb + bLane + (uint32_t)((kk * 16 * KVST + nfp * 16) * 2);
                asm volatile(
                    "ldmatrix.sync.aligned.m8n8.x4.trans.shared.b16 {%0,%1,%2,%3}, [%4];"
                    : "=r"(bf[nfp * 2][0]), "=r"(bf[nfp * 2][1]),
                      "=r"(bf[nfp * 2 + 1][0]), "=r"(bf[nfp * 2 + 1][1])
                    : "r"(baddr));
            }
#pragma unroll
            for (int nf = 0; nf < 8; nf++)
                asm volatile(
                    "mma.sync.aligned.m16n8k16.row.col.f32.f16.f16.f32 "
                    "{%0,%1,%2,%3}, {%4,%5,%6,%7}, {%8,%9}, {%0,%1,%2,%3};"
                    : "+f"(acc[nf][0]), "+f"(acc[nf][1]), "+f"(acc[nf][2]), "+f"(acc[nf][3])
                    : "r"(a[0]), "r"(a[1]), "r"(a[2]), "r"(a[3]),
                      "r"(bf[nf][0]), "r"(bf[nf][1]));
        }
        __syncthreads();
    }

    float* kvo = kvp + ((size_t)ch * 64 + bh) * 4096;
    const int gr = lane >> 2, gc2 = (lane & 3) * 2;
#pragma unroll
    for (int nf = 0; nf < 8; nf++) {
        int col = nf * 8 + gc2;
        *(float2*)(kvo + (d0 + gr) * 64 + col) = make_float2(acc[nf][0], acc[nf][1]);
        *(float2*)(kvo + (d0 + gr + 8) * 64 + col) = make_float2(acc[nf][2], acc[nf][3]);
    }
}

__global__ void reduce_kv(const float* __restrict__ kvp, __half* __restrict__ kvTh) {
    int i = blockIdx.x * 256 + threadIdx.x;
    int bh = i >> 12, idx = i & 4095;
    int d = idx >> 6, e = idx & 63;
    float s = 0.f;
#pragma unroll
    for (int c = 0; c < KCH; c++) s += kvp[((size_t)c * 64 + bh) * 4096 + idx];
    kvTh[(size_t)bh * 4096 + e * 64 + d] = __float2half_rn(s);
}

__global__ void __launch_bounds__(256) ksum_kernel(const __half* __restrict__ Kh,
                                                   float* __restrict__ ks) {
    const int bh = blockIdx.x;
    const int b = bh >> 4, h = bh & 15;
    const int d = threadIdx.x & 63, sl = threadIdx.x >> 6;
    const __half* Kbase = Kh + (size_t)b * SEQ * D_MODEL + h * 64 + d;
    float s = 0.f;
    for (int ss = sl; ss < SEQ; ss += 4) s += __half2float(Kbase[(size_t)ss * D_MODEL]);
    __shared__ float red[256];
    red[threadIdx.x] = s;
    __syncthreads();
    if (threadIdx.x < 64)
        ks[bh * 64 + d] = red[d] + red[d + 64] + red[d + 128] + red[d + 192];
}

__global__ void __launch_bounds__(128) attn_tc(const __half* __restrict__ Qh,
                                               const __half* __restrict__ kvTh,
                                               const float* __restrict__ ksum,
                                               __half* __restrict__ Ah) {
    const int bh = blockIdx.x;
    const int b = bh >> 4, h = bh & 15;
    const int s0 = blockIdx.y * 64;
    __shared__ __half qs[64 * KVST];
    __shared__ __half kvs[64 * KVST];
    __shared__ float kss[64];

    const int tid = threadIdx.x;
    const int lane = tid & 31, w = tid >> 5;
    const int m0w = w * 16;

    uint32_t qsb, kvb;
    asm("{ .reg .u64 t; cvta.to.shared.u64 t, %1; cvt.u32.u64 %0, t; }" : "=r"(qsb) : "l"(qs));
    asm("{ .reg .u64 t; cvta.to.shared.u64 t, %1; cvt.u32.u64 %0, t; }" : "=r"(kvb) : "l"(kvs));

    for (int j = 0; j < 4; j++) {
        int c = tid + j * 128;
        int row = c >> 3, col8 = (c & 7) * 8;
        *(uint4*)&qs[row * KVST + col8] =
            *(const uint4*)(Qh + (size_t)(b * SEQ + s0 + row) * 1024 + h * 64 + col8);
        *(uint4*)&kvs[row * KVST + col8] =
            *(const uint4*)(kvTh + (size_t)bh * 4096 + row * 64 + col8);
    }
    if (tid < 64) kss[tid] = ksum[bh * 64 + tid];
    __syncthreads();

    const uint32_t aLane = (uint32_t)(((m0w + (lane & 15)) * KVST + (lane >> 4) * 8) * 2);
    const uint32_t bLane = (uint32_t)(((((lane >> 4) & 1) * 8 + (lane & 7)) * KVST +
                                       ((lane >> 3) & 1) * 8) * 2);

    float acc[8][4];
#pragma unroll
    for (int i = 0; i < 8; i++)
#pragma unroll
        for (int j = 0; j < 4; j++) acc[i][j] = 0.0f;

#pragma unroll
    for (int kk = 0; kk < 4; kk++) {
        uint32_t a[4];
        uint32_t aaddr = qsb + aLane + (uint32_t)(kk * 32);
        asm volatile(
            "ldmatrix.sync.aligned.m8n8.x4.shared.b16 {%0,%1,%2,%3}, [%4];"
            : "=r"(a[0]), "=r"(a[1]), "=r"(a[2]), "=r"(a[3]) : "r"(aaddr));
        uint32_t bf[8][2];
#pragma unroll
        for (int nfp = 0; nfp < 4; nfp++) {
            uint32_t baddr = kvb + bLane + (uint32_t)((nfp * 16 * KVST + kk * 16) * 2);
            asm volatile(
                "ldmatrix.sync.aligned.m8n8.x4.shared.b16 {%0,%1,%2,%3}, [%4];"
                : "=r"(bf[nfp * 2][0]), "=r"(bf[nfp * 2][1]),
                  "=r"(bf[nfp * 2 + 1][0]), "=r"(bf[nfp * 2 + 1][1])
                : "r"(baddr));
        }
#pragma unroll
        for (int nf = 0; nf < 8; nf++)
            asm volatile(
                "mma.sync.aligned.m16n8k16.row.col.f32.f16.f16.f32 "
                "{%0,%1,%2,%3}, {%4,%5,%6,%7}, {%8,%9}, {%0,%1,%2,%3};"
                : "+f"(acc[nf][0]), "+f"(acc[nf][1]), "+f"(acc[nf][2]), "+f"(acc[nf][3])
                : "r"(a[0]), "r"(a[1]), "r"(a[2]), "r"(a[3]),
                  "r"(bf[nf][0]), "r"(bf[nf][1]));
    }

    const int gr = lane >> 2, gc2 = (lane & 3) * 2;
    float z0 = 0.f, z1 = 0.f;
#pragma unroll 8
    for (int d = 0; d < 64; d++) {
        float kd = kss[d];
        z0 = fmaf(__half2float(qs[(m0w + gr) * KVST + d]), kd, z0);
        z1 = fmaf(__half2float(qs[(m0w + gr + 8) * KVST + d]), kd, z1);
    }
    const float iz0 = 1.0f / (z0 + EPS), iz1 = 1.0f / (z1 + EPS);

    __half* Aout = Ah + (size_t)(b * SEQ + s0 + m0w) * 1024 + h * 64;
#pragma unroll
    for (int nf = 0; nf < 8; nf++) {
        int col = nf * 8 + gc2;
        *(__half2*)(Aout + (size_t)gr * 1024 + col) =
            __floats2half2_rn(acc[nf][0] * iz0, acc[nf][1] * iz0);
        *(__half2*)(Aout + (size_t)(gr + 8) * 1024 + col) =
            __floats2half2_rn(acc[nf][2] * iz1, acc[nf][3] * iz1);
    }
}

// ---------------- launch ----------------
extern "C" void kernel_launch(void* const* d_in, const int* in_sizes, int n_in,
                              void* d_out, int out_size) {
    const float* x  = (const float*)d_in[0];
    const float* Wq = (const float*)d_in[1];
    const float* bq = (const float*)d_in[2];
    const float* Wk = (const float*)d_in[3];
    const float* bk = (const float*)d_in[4];
    const float* Wv = (const float*)d_in[5];
    const float* bv = (const float*)d_in[6];
    const float* Wo = (const float*)d_in[7];
    const float* bo = (const float*)d_in[8];
    float* out = (float*)d_out;

    __half *Xh, *Ah, *Qh, *Kh, *Vh, *Wh, *kvTh;
    float *bqkv, *kvp, *ks;
    cudaGetSymbolAddress((void**)&Xh, g_Xh);
    cudaGetSymbolAddress((void**)&Ah, g_Ah);
    cudaGetSymbolAddress((void**)&Qh, g_Qh);
    cudaGetSymbolAddress((void**)&Kh, g_Kh);
    cudaGetSymbolAddress((void**)&Vh, g_Vh);
    cudaGetSymbolAddress((void**)&Wh, g_Wh);
    cudaGetSymbolAddress((void**)&kvTh, g_kvTh);
    cudaGetSymbolAddress((void**)&bqkv, g_bqkv);
    cudaGetSymbolAddress((void**)&kvp, g_kvp);
    cudaGetSymbolAddress((void**)&ks, g_ks);

    cudaFuncSetAttribute(gemm_wt64<1, __half>, cudaFuncAttributeMaxDynamicSharedMemorySize,
                         GEMM_SMEM);
    cudaFuncSetAttribute(gemm_wt64<0, float>, cudaFuncAttributeMaxDynamicSharedMemorySize,
                         GEMM_SMEM);

    const size_t WN = (size_t)D_MODEL * D_MODEL;

    to_half_kernel<<<NTOK * D_MODEL / 4 / 256, 256>>>((const float4*)x, (__half2*)Xh,
                                                      NTOK * D_MODEL / 4);
    transpose_half4<<<dim3(32, 32, 4), dim3(32, 8)>>>(Wq, Wk, Wv, Wo, Wh);
    pack_bias<<<12, 256>>>(bq, bk, bv, bqkv);

    // fused QKV: N = 3072
    gemm_wt64<1, __half><<<dim3(24, 128), 128, GEMM_SMEM>>>(Xh, Wh, bqkv, Qh, Kh, Vh);

    kv_tc<<<dim3(64, KCH), 128>>>(Kh, Vh, kvp);
    reduce_kv<<<(64 * 4096) / 256, 256>>>(kvp, kvTh);
    ksum_kernel<<<64, 256>>>(Kh, ks);
    attn_tc<<<dim3(64, SEQ / 64), 128>>>(Qh, kvTh, ks, Ah);

    gemm_wt64<0, float><<<dim3(8, 128), 128, GEMM_SMEM>>>(Ah, Wh + 3 * WN, bo, out, out, out);
}